// round 4
// baseline (speedup 1.0000x reference)
#include <cuda_runtime.h>
#include <cuda_bf16.h>
#include <cuda_fp16.h>
#include <mma.h>

using namespace nvcuda;

#define F 128
#define N_NODES_MAX 100000
#define N_ROWS_PAD 100224   // 782*128 = 100096 <= pad
#define E_MAX 600000

// ---- scratch (__device__ globals; allocation-free rule) --------------------
__device__ __half g_support_h[(size_t)N_ROWS_PAD * F];   // fp16 support
__device__ __nv_bfloat16 g_whi[F * F];                    // W hi split
__device__ __nv_bfloat16 g_wlo[F * F];                    // W lo split
__device__ int g_cnt[N_NODES_MAX];                        // per-row edge count
__device__ int g_off[N_NODES_MAX + 1];                    // exclusive offsets
__device__ int g_pos[N_NODES_MAX];                        // atomic bump cursor
__device__ int2 g_cv[2 * E_MAX];                          // sorted (col, valbits)

// ---------------------------------------------------------------------------
// W split: w -> bf16 hi/lo (once per call; 16384 elems)
// ---------------------------------------------------------------------------
__global__ void wsplit_kernel(const float* __restrict__ w) {
    int i = blockIdx.x * blockDim.x + threadIdx.x;
    float f = w[i];
    __nv_bfloat16 h = __float2bfloat16_rn(f);
    g_whi[i] = h;
    g_wlo[i] = __float2bfloat16_rn(f - __bfloat162float(h));
}

// ---------------------------------------------------------------------------
// GEMM: support_h[n,128] = fp16( x[n,128] @ w[128,128] ), BF16x3 compensated.
// Block 256 thr (8 warps), tile 128x128. Warp tile 32x64 (warp grid 4x2).
// x hi/lo staged in smem per 64-wide K tile; W frags loaded from global
// (L1-hot). 2 CTAs/SM via launch_bounds.
// ---------------------------------------------------------------------------
__global__ void __launch_bounds__(256, 2) gemm_bf16x3_kernel(
    const float* __restrict__ x, int n) {
    __shared__ __nv_bfloat16 xs_hi[128][72];  // 18 KB
    __shared__ __nv_bfloat16 xs_lo[128][72];  // 18 KB

    const int tid = threadIdx.x;
    const int wid = tid >> 5;
    const int lane = tid & 31;
    const int warp_m = wid & 3;   // 32-row band
    const int warp_n = wid >> 2;  // 64-col band
    const int row0 = blockIdx.x * 128;

    wmma::fragment<wmma::accumulator, 16, 16, 16, float> acc[2][4];
    #pragma unroll
    for (int i = 0; i < 2; i++)
        #pragma unroll
        for (int j = 0; j < 4; j++) wmma::fill_fragment(acc[i][j], 0.0f);

    for (int kt = 0; kt < 2; kt++) {  // two K tiles of 64
        // x tile 128x64: 2048 float4, 8 per thread; split to hi/lo bf16
        #pragma unroll
        for (int i = tid; i < 2048; i += 256) {
            int r = i >> 4;
            int c = (i & 15) * 4;
            int row = row0 + r;
            float4 v = make_float4(0.f, 0.f, 0.f, 0.f);
            if (row < n)
                v = *(const float4*)&x[(size_t)row * F + kt * 64 + c];
            float f[4] = {v.x, v.y, v.z, v.w};
            #pragma unroll
            for (int q = 0; q < 4; q++) {
                __nv_bfloat16 h = __float2bfloat16_rn(f[q]);
                xs_hi[r][c + q] = h;
                xs_lo[r][c + q] = __float2bfloat16_rn(f[q] - __bfloat162float(h));
            }
        }
        __syncthreads();

        #pragma unroll
        for (int ks = 0; ks < 4; ks++) {  // 4 k-steps of 16
            wmma::fragment<wmma::matrix_a, 16, 16, 16, __nv_bfloat16,
                           wmma::row_major> a_hi[2], a_lo[2];
            #pragma unroll
            for (int i = 0; i < 2; i++) {
                wmma::load_matrix_sync(a_hi[i],
                                       &xs_hi[warp_m * 32 + i * 16][ks * 16], 72);
                wmma::load_matrix_sync(a_lo[i],
                                       &xs_lo[warp_m * 32 + i * 16][ks * 16], 72);
            }
            #pragma unroll
            for (int j = 0; j < 4; j++) {
                wmma::fragment<wmma::matrix_b, 16, 16, 16, __nv_bfloat16,
                               wmma::row_major> b_hi, b_lo;
                size_t wofs = (size_t)(kt * 64 + ks * 16) * F + warp_n * 64 + j * 16;
                wmma::load_matrix_sync(b_hi, &g_whi[wofs], F);
                wmma::load_matrix_sync(b_lo, &g_wlo[wofs], F);
                #pragma unroll
                for (int i = 0; i < 2; i++) {
                    wmma::mma_sync(acc[i][j], a_hi[i], b_hi, acc[i][j]);
                    wmma::mma_sync(acc[i][j], a_hi[i], b_lo, acc[i][j]);
                    wmma::mma_sync(acc[i][j], a_lo[i], b_hi, acc[i][j]);
                }
            }
        }
        __syncthreads();
    }

    // Epilogue: stage each 16x16 frag via smem (reuse xs_hi), write fp16.
    float* stage = (float*)&xs_hi[0][0] + wid * 320;  // 16x20 floats per warp
    #pragma unroll
    for (int i = 0; i < 2; i++)
        #pragma unroll
        for (int j = 0; j < 4; j++) {
            wmma::store_matrix_sync(stage, acc[i][j], 20, wmma::mem_row_major);
            __syncwarp();
            int r = lane >> 1;
            int c = (lane & 1) * 8;
            __half hbuf[8];
            #pragma unroll
            for (int q = 0; q < 8; q++)
                hbuf[q] = __float2half_rn(stage[r * 20 + c + q]);
            size_t row = (size_t)row0 + warp_m * 32 + i * 16 + r;
            *(uint4*)&g_support_h[row * F + warp_n * 64 + j * 16 + c] =
                *(uint4*)hbuf;
            __syncwarp();
        }
}

// ---------------------------------------------------------------------------
// Counting sort of edges by destination row
// ---------------------------------------------------------------------------
__global__ void zero_cnt_kernel(int n) {
    int i = blockIdx.x * blockDim.x + threadIdx.x;
    if (i < n) g_cnt[i] = 0;
}

__global__ void hist_kernel(const int* __restrict__ rows0,
                            const int* __restrict__ rows1, int E) {
    int i = blockIdx.x * blockDim.x + threadIdx.x;
    if (i >= 2 * E) return;
    int r = (i < E) ? __ldg(&rows0[i]) : __ldg(&rows1[i - E]);
    atomicAdd(&g_cnt[r], 1);
}

// single-block exclusive scan of g_cnt -> g_off, g_pos
__global__ void __launch_bounds__(1024) scan_kernel(int n) {
    __shared__ int sums[1024];
    int t = threadIdx.x;
    int chunk = (n + 1023) >> 10;
    int b0 = t * chunk;
    int b1 = min(n, b0 + chunk);
    int s = 0;
    for (int i = b0; i < b1; i++) s += g_cnt[i];
    sums[t] = s;
    __syncthreads();
    #pragma unroll
    for (int off = 1; off < 1024; off <<= 1) {
        int v = (t >= off) ? sums[t - off] : 0;
        __syncthreads();
        sums[t] += v;
        __syncthreads();
    }
    int run = (t == 0) ? 0 : sums[t - 1];
    for (int i = b0; i < b1; i++) {
        g_off[i] = run;
        g_pos[i] = run;
        run += g_cnt[i];
    }
    if (t == 1023) g_off[n] = sums[1023];
}

__global__ void binsort_kernel(
    const float* __restrict__ vals0, const int* __restrict__ rows0,
    const int* __restrict__ cols0,
    const float* __restrict__ vals1, const int* __restrict__ rows1,
    const int* __restrict__ cols1, int E) {
    int i = blockIdx.x * blockDim.x + threadIdx.x;
    if (i >= 2 * E) return;
    int r, c;
    float v;
    if (i < E) {
        r = __ldg(&rows0[i]); c = __ldg(&cols0[i]); v = __ldg(&vals0[i]);
    } else {
        r = __ldg(&rows1[i - E]); c = __ldg(&cols1[i - E]); v = __ldg(&vals1[i - E]);
    }
    int pos = atomicAdd(&g_pos[r], 1);
    g_cv[pos] = make_int2(c, __float_as_int(v));
}

// ---------------------------------------------------------------------------
// Segmented gather: one warp per destination row.
//   out[row] = bias + sum_{e in row's bin} support_h[col_e] * val_e
// No atomics. Lane owns 4 features (float4 acc). 256B fp16 gather per edge.
// ---------------------------------------------------------------------------
__global__ void __launch_bounds__(256) gather_kernel(
    const float* __restrict__ bias, float* __restrict__ out, int n) {
    int gw = (blockIdx.x * blockDim.x + threadIdx.x) >> 5;
    int lane = threadIdx.x & 31;
    if (gw >= n) return;

    int start = g_off[gw];
    int end = g_off[gw + 1];

    float4 acc = __ldg(&((const float4*)bias)[lane]);
    const uint2* sup = (const uint2*)g_support_h;

    for (int base = start; base < end; base += 32) {
        int m = min(32, end - base);
        int2 cv = make_int2(0, 0);
        if (lane < m) cv = __ldg(&g_cv[base + lane]);
        for (int i = 0; i < m; i++) {
            int cc = __shfl_sync(0xffffffff, cv.x, i);
            float vv = __int_as_float(__shfl_sync(0xffffffff, cv.y, i));
            uint2 p = __ldg(&sup[(size_t)cc * (F / 4) + lane]);
            float2 f01 = __half22float2(*(__half2*)&p.x);
            float2 f23 = __half22float2(*(__half2*)&p.y);
            acc.x += f01.x * vv;
            acc.y += f01.y * vv;
            acc.z += f23.x * vv;
            acc.w += f23.y * vv;
        }
    }
    *(float4*)&out[(size_t)gw * F + lane * 4] = acc;
}

// ---------------------------------------------------------------------------
// kernel_launch
// inputs: x, weight, bias, vals0, vals1, rows0, cols0, rows1, cols1
// ---------------------------------------------------------------------------
extern "C" void kernel_launch(void* const* d_in, const int* in_sizes, int n_in,
                              void* d_out, int out_size) {
    const float* x     = (const float*)d_in[0];
    const float* w     = (const float*)d_in[1];
    const float* bias  = (const float*)d_in[2];
    const float* vals0 = (const float*)d_in[3];
    const float* vals1 = (const float*)d_in[4];
    const int* rows0   = (const int*)d_in[5];
    const int* cols0   = (const int*)d_in[6];
    const int* rows1   = (const int*)d_in[7];
    const int* cols1   = (const int*)d_in[8];
    float* out = (float*)d_out;

    int n = in_sizes[0] / F;   // 100000
    int E = in_sizes[3];       // 600000

    // ---- edge binning chain (independent of GEMM) ----
    zero_cnt_kernel<<<(n + 255) / 256, 256>>>(n);
    int eblocks = (2 * E + 255) / 256;
    hist_kernel<<<eblocks, 256>>>(rows0, rows1, E);
    scan_kernel<<<1, 1024>>>(n);
    binsort_kernel<<<eblocks, 256>>>(vals0, rows0, cols0, vals1, rows1, cols1, E);

    // ---- GEMM: support_h = fp16(x @ W) ----
    wsplit_kernel<<<(F * F) / 256, 256>>>(w);
    gemm_bf16x3_kernel<<<(n + 127) / 128, 256>>>(x, n);

    // ---- segmented gather + bias (no atomics) ----
    int gblocks = (n * 32 + 255) / 256;
    gather_kernel<<<gblocks, 256>>>(bias, out, n);
}

// round 5
// speedup vs baseline: 1.9954x; 1.9954x over previous
#include <cuda_runtime.h>
#include <cuda_bf16.h>
#include <cuda_fp16.h>
#include <mma.h>

using namespace nvcuda;

#define F 128
#define N_NODES_MAX 100000
#define N_ROWS_PAD 100096  // 1564 * 64 = 100096 (tile M=64)

// fp16 support (only consumer is the scatter)
__device__ __half g_support_h[(size_t)N_ROWS_PAD * F];
__device__ __nv_bfloat16 g_whi[F * F];  // W hi split (bf16)
__device__ __nv_bfloat16 g_wlo[F * F];  // W lo split (bf16)

// ---------------------------------------------------------------------------
// W split: w -> bf16 hi/lo, once (16384 elems, ~2us)
// ---------------------------------------------------------------------------
__global__ void wsplit_kernel(const float* __restrict__ w) {
    int i = blockIdx.x * blockDim.x + threadIdx.x;
    float f = w[i];
    __nv_bfloat16 h = __float2bfloat16_rn(f);
    g_whi[i] = h;
    g_wlo[i] = __float2bfloat16_rn(f - __bfloat162float(h));
}

// ---------------------------------------------------------------------------
// GEMM: support_h[n,128] = fp16( x[n,128] @ w[128,128] ), BF16x3 compensated.
// Block 128 thr (4 warps), tile 64(M) x 128(N). Warp tile 32x64:
//   warp_m = wid&1 (32-row band), warp_n = wid>>1 (64-col band).
// K tiled 4x32. x hi/lo split into smem; W tiles copied from presplit global.
// 3 CTAs/SM (17.2K regs, ~27KB smem per CTA).
// ---------------------------------------------------------------------------
__global__ void __launch_bounds__(128, 3) gemm_bf16x3_kernel(
    const float* __restrict__ x, int n) {
    __shared__ __nv_bfloat16 xs_hi[64][40];   // 5.0 KB
    __shared__ __nv_bfloat16 xs_lo[64][40];   // 5.0 KB
    __shared__ __nv_bfloat16 ws_hi[32][136];  // 8.5 KB
    __shared__ __nv_bfloat16 ws_lo[32][136];  // 8.5 KB

    const int tid = threadIdx.x;
    const int wid = tid >> 5;
    const int lane = tid & 31;
    const int warp_m = wid & 1;   // 32-row band
    const int warp_n = wid >> 1;  // 64-col band
    const int row0 = blockIdx.x * 64;

    wmma::fragment<wmma::accumulator, 16, 16, 16, float> acc[2][4];
    #pragma unroll
    for (int i = 0; i < 2; i++)
        #pragma unroll
        for (int j = 0; j < 4; j++) wmma::fill_fragment(acc[i][j], 0.0f);

    for (int kt = 0; kt < 4; kt++) {
        // x tile 64x32: 512 float4, 4 per thread; split to hi/lo bf16
        #pragma unroll
        for (int i = tid; i < 512; i += 128) {
            int r = i >> 3;
            int c = (i & 7) * 4;
            int row = row0 + r;
            float4 v = make_float4(0.f, 0.f, 0.f, 0.f);
            if (row < n)
                v = *(const float4*)&x[(size_t)row * F + kt * 32 + c];
            float f[4] = {v.x, v.y, v.z, v.w};
            #pragma unroll
            for (int q = 0; q < 4; q++) {
                __nv_bfloat16 h = __float2bfloat16_rn(f[q]);
                xs_hi[r][c + q] = h;
                xs_lo[r][c + q] = __float2bfloat16_rn(f[q] - __bfloat162float(h));
            }
        }
        // w tile 32x128: copy presplit bf16 (512 uint4 loads per array half)
        #pragma unroll
        for (int i = tid; i < 512; i += 128) {
            int r = i >> 4;            // 16 x 8-elem chunks per row
            int c = (i & 15) * 8;
            size_t src = (size_t)(kt * 32 + r) * F + c;
            *(uint4*)&ws_hi[r][c] = *(const uint4*)&g_whi[src];
            *(uint4*)&ws_lo[r][c] = *(const uint4*)&g_wlo[src];
        }
        __syncthreads();

        #pragma unroll
        for (int ks = 0; ks < 2; ks++) {  // 2 k-steps of 16
            wmma::fragment<wmma::matrix_a, 16, 16, 16, __nv_bfloat16,
                           wmma::row_major> a_hi[2], a_lo[2];
            #pragma unroll
            for (int i = 0; i < 2; i++) {
                wmma::load_matrix_sync(a_hi[i],
                                       &xs_hi[warp_m * 32 + i * 16][ks * 16], 40);
                wmma::load_matrix_sync(a_lo[i],
                                       &xs_lo[warp_m * 32 + i * 16][ks * 16], 40);
            }
            #pragma unroll
            for (int j = 0; j < 4; j++) {
                wmma::fragment<wmma::matrix_b, 16, 16, 16, __nv_bfloat16,
                               wmma::row_major> b_hi, b_lo;
                wmma::load_matrix_sync(b_hi,
                                       &ws_hi[ks * 16][warp_n * 64 + j * 16], 136);
                wmma::load_matrix_sync(b_lo,
                                       &ws_lo[ks * 16][warp_n * 64 + j * 16], 136);
                #pragma unroll
                for (int i = 0; i < 2; i++) {
                    wmma::mma_sync(acc[i][j], a_hi[i], b_hi, acc[i][j]);
                    wmma::mma_sync(acc[i][j], a_hi[i], b_lo, acc[i][j]);
                    wmma::mma_sync(acc[i][j], a_lo[i], b_hi, acc[i][j]);
                }
            }
        }
        __syncthreads();
    }

    // Epilogue: stage each 16x16 frag via smem (reuse xs region), write fp16.
    float* stage = (float*)&xs_hi[0][0] + wid * 320;  // 16x20 floats per warp
    #pragma unroll
    for (int i = 0; i < 2; i++)
        #pragma unroll
        for (int j = 0; j < 4; j++) {
            wmma::store_matrix_sync(stage, acc[i][j], 20, wmma::mem_row_major);
            __syncwarp();
            int r = lane >> 1;
            int c = (lane & 1) * 8;
            __half hbuf[8];
            #pragma unroll
            for (int q = 0; q < 8; q++)
                hbuf[q] = __float2half_rn(stage[r * 20 + c + q]);
            size_t row = (size_t)row0 + warp_m * 32 + i * 16 + r;
            *(uint4*)&g_support_h[row * F + warp_n * 64 + j * 16 + c] =
                *(uint4*)hbuf;
            __syncwarp();
        }
}

// ---------------------------------------------------------------------------
// out[i][f] = bias[f]
// ---------------------------------------------------------------------------
__global__ void bias_init_kernel(const float* __restrict__ bias,
                                 float* __restrict__ out, int n) {
    size_t idx = (size_t)blockIdx.x * blockDim.x + threadIdx.x;
    size_t total = (size_t)n * (F / 4);
    float4* out4 = (float4*)out;
    const float4* b4 = (const float4*)bias;
    for (size_t i = idx; i < total; i += (size_t)gridDim.x * blockDim.x) {
        out4[i] = b4[i & (F / 4 - 1)];
    }
}

// ---------------------------------------------------------------------------
// Edge scatter (both edge sets, one launch):
//   out[rows[e]] += support_h[cols[e]] * vals[e]
// Warp owns 32 edges: coalesced index loads + shfl broadcast.
// 8B fp16 gather per lane; one red.global.add.v4.f32 per lane per edge.
// ---------------------------------------------------------------------------
__global__ void __launch_bounds__(256) scatter_kernel(
    const float* __restrict__ vals0, const int* __restrict__ rows0,
    const int* __restrict__ cols0,
    const float* __restrict__ vals1, const int* __restrict__ rows1,
    const int* __restrict__ cols1,
    float* __restrict__ out, int E) {
    int gw = (blockIdx.x * blockDim.x + threadIdx.x) >> 5;
    int lane = threadIdx.x & 31;
    int warps_per_set = (E + 31) >> 5;
    if (gw >= 2 * warps_per_set) return;

    const float* vals;
    const int* rows;
    const int* cols;
    int wset = gw;
    if (gw < warps_per_set) {
        vals = vals0; rows = rows0; cols = cols0;
    } else {
        vals = vals1; rows = rows1; cols = cols1; wset = gw - warps_per_set;
    }
    int base = wset * 32;

    int e = base + lane;
    bool valid = e < E;
    float v = valid ? __ldg(&vals[e]) : 0.f;
    int r = valid ? __ldg(&rows[e]) : 0;
    int c = valid ? __ldg(&cols[e]) : 0;

    int cnt = min(32, E - base);
    const uint2* sup = (const uint2*)g_support_h;

    #pragma unroll 4
    for (int i = 0; i < cnt; i++) {
        int rr = __shfl_sync(0xffffffff, r, i);
        int cc = __shfl_sync(0xffffffff, c, i);
        float vv = __shfl_sync(0xffffffff, v, i);

        uint2 packed = __ldg(&sup[(size_t)cc * (F / 4) + lane]);
        float2 f01 = __half22float2(*(__half2*)&packed.x);
        float2 f23 = __half22float2(*(__half2*)&packed.y);

        float* dst = out + (size_t)rr * F + lane * 4;
        asm volatile("red.global.add.v4.f32 [%0], {%1,%2,%3,%4};"
                     :: "l"(dst), "f"(f01.x * vv), "f"(f01.y * vv),
                        "f"(f23.x * vv), "f"(f23.y * vv)
                     : "memory");
    }
}

// ---------------------------------------------------------------------------
// kernel_launch
// inputs: x, weight, bias, vals0, vals1, rows0, cols0, rows1, cols1
// ---------------------------------------------------------------------------
extern "C" void kernel_launch(void* const* d_in, const int* in_sizes, int n_in,
                              void* d_out, int out_size) {
    const float* x     = (const float*)d_in[0];
    const float* w     = (const float*)d_in[1];
    const float* bias  = (const float*)d_in[2];
    const float* vals0 = (const float*)d_in[3];
    const float* vals1 = (const float*)d_in[4];
    const int* rows0   = (const int*)d_in[5];
    const int* cols0   = (const int*)d_in[6];
    const int* rows1   = (const int*)d_in[7];
    const int* cols1   = (const int*)d_in[8];
    float* out = (float*)d_out;

    int n = in_sizes[0] / F;   // 100000
    int E = in_sizes[3];       // 600000

    // 1) W hi/lo split, then support_h = fp16(x @ W)
    wsplit_kernel<<<(F * F) / 256, 256>>>(w);
    gemm_bf16x3_kernel<<<(n + 63) / 64, 128>>>(x, n);

    // 2) out = bias
    bias_init_kernel<<<2048, 256>>>(bias, out, n);

    // 3) scatter both edge sets (one launch, vector reds)
    long long total_warps = 2LL * ((E + 31) / 32);
    int sblocks = (int)((total_warps * 32 + 255) / 256);
    scatter_kernel<<<sblocks, 256>>>(vals0, rows0, cols0, vals1, rows1, cols1,
                                     out, E);
}